// round 3
// baseline (speedup 1.0000x reference)
#include <cuda_runtime.h>
#include <cuda_bf16.h>

// GruDirection3d forward wavefront:
//   out[d,y,x] = z*h_tilde + (1-z)*out[d-1,y-1,x-1],  border -> h0
//
// Shifted coordinates u=y-d, v=x-d turn the 3D diagonal recurrence into
// 63x63 INDEPENDENT scans along d (per (u,v) chain): the spatial shift
// vanishes, so there is no cross-thread dependency at all. No smem, no
// barriers. Warp lanes map to consecutive v -> every step's active loads
// and stores are contiguous (addr = base + u*32 + v + d*1057), each voxel
// is read/written exactly once (minimal 75.5MB traffic). The per-chain
// serial dependency is only the fmaf accumulator; all load addresses are
// accumulator-independent, so the full unroll exposes deep MLP.

#define VOLE 32768              // 32*32*32 elements per (b,c) volume
#define STEP 1057               // 1024 + 32 + 1: address delta per d along a chain

__global__ __launch_bounds__(256)
void gru3d_chain(const float* __restrict__ z,
                 const float* __restrict__ ht,
                 const float* __restrict__ h0p,
                 float*       __restrict__ out)
{
    const float h0 = __ldg(h0p);
    const int tid  = threadIdx.x;

    // 64 lanes of v per u-row; 4 u-rows per CTA; 16 CTAs cover u in [-31,32].
    const int v   = (tid & 63) - 32;                       // -32..31 (-32 never active)
    const int u   = ((int)(blockIdx.x & 15)) * 4 + (tid >> 6) - 31;  // -31..32
    const int vol = blockIdx.x >> 4;

    // Active window in d: both u+d and v+d must lie in [0,32).
    int d0 = 0;
    if (-u > d0) d0 = -u;
    if (-v > d0) d0 = -v;
    int d1 = 32;
    if (32 - u < d1) d1 = 32 - u;
    if (32 - v < d1) d1 = 32 - v;

    const size_t vbase = (size_t)vol * VOLE;
    const float* zp = z  + vbase;
    const float* hp = ht + vbase;
    float*       op = out + vbase;

    const int base0 = u * 32 + v;   // index at d=0 (may be negative; guarded)

    // At the window start one of {d, u+d, v+d} is 0, so prev is the h0 border.
    float o = h0;

    #pragma unroll
    for (int d = 0; d < 32; ++d) {
        if (d >= d0 && d < d1) {
            const int idx = base0 + d * STEP;
            const float zz = zp[idx];
            const float hh = hp[idx];
            o = fmaf(zz, hh - o, o);     // z*ht + (1-z)*prev
            op[idx] = o;
        }
    }
}

extern "C" void kernel_launch(void* const* d_in, const int* in_sizes, int n_in,
                              void* d_out, int out_size)
{
    const float* z  = (const float*)d_in[0];
    const float* ht = (const float*)d_in[1];
    const float* h0 = (const float*)d_in[2];
    float* out = (float*)d_out;

    const int n_volumes = out_size / VOLE;   // B*C = 192
    gru3d_chain<<<n_volumes * 16, 256>>>(z, ht, h0, out);
}